// round 14
// baseline (speedup 1.0000x reference)
#include <cuda_runtime.h>
#include <cstdint>

// sLSTM, T=512, B=16, HID=1024, H=4 heads (D=256), G=4 gates.
// R14 = R13 skeleton (cluster-of-8 DSMEM bulk exchange, W in regs, f32x2 GEMM)
// + chain shortening: per-warp parallel copy issue (mapa hoisted), x prefetched
// a full step ahead, butterfly reduce-scatter (14 shfls), arm-before-wait,
// out-store after copy issue.

#define T_STEPS 512
#define BATCH   16
#define HID     1024
#define TPB     256
#define SRS     17
#define CLUSTER 8
#define TXB     4096u    // 8 copies x 512 B per receiver per step

__device__ __forceinline__ void ffma2(unsigned long long &acc,
                                      unsigned long long a,
                                      unsigned long long b) {
    asm("fma.rn.f32x2 %0, %1, %2, %0;" : "+l"(acc) : "l"(a), "l"(b));
}
__device__ __forceinline__ float fold2(unsigned long long a) {
    return __uint_as_float((unsigned)(a & 0xffffffffu)) +
           __uint_as_float((unsigned)(a >> 32));
}
__device__ __forceinline__ uint32_t smem_u32(const void* p) {
    uint32_t a;
    asm("{ .reg .u64 t; cvta.to.shared.u64 t, %1; cvt.u32.u64 %0, t; }"
        : "=r"(a) : "l"(p));
    return a;
}
__device__ __forceinline__ uint32_t mapa_u32(uint32_t a, uint32_t rank) {
    uint32_t d;
    asm("mapa.shared::cluster.u32 %0, %1, %2;" : "=r"(d) : "r"(a), "r"(rank));
    return d;
}
__device__ __forceinline__ void bulk_copy_s2s(uint32_t dst_cluster, uint32_t src_cta,
                                              uint32_t bytes, uint32_t mbar_cluster) {
    asm volatile(
        "cp.async.bulk.shared::cluster.shared::cta.mbarrier::complete_tx::bytes "
        "[%0], [%1], %2, [%3];"
        :: "r"(dst_cluster), "r"(src_cta), "r"(bytes), "r"(mbar_cluster) : "memory");
}
__device__ __forceinline__ void mbar_init(uint32_t mbar, uint32_t cnt) {
    asm volatile("mbarrier.init.shared.b64 [%0], %1;" :: "r"(mbar), "r"(cnt) : "memory");
}
__device__ __forceinline__ void mbar_expect_tx(uint32_t mbar, uint32_t bytes) {
    asm volatile("mbarrier.arrive.expect_tx.shared.b64 _, [%0], %1;"
                 :: "r"(mbar), "r"(bytes) : "memory");
}
__device__ __forceinline__ void mbar_wait(uint32_t mbar, uint32_t parity) {
    uint32_t done;
    asm volatile(
        "{\n\t.reg .pred p;\n\t"
        "mbarrier.try_wait.parity.acquire.cta.shared::cta.b64 p, [%1], %2;\n\t"
        "selp.b32 %0, 1, 0, p;\n\t}"
        : "=r"(done) : "r"(mbar), "r"(parity) : "memory");
    if (!done) {
        asm volatile(
            "{\n\t.reg .pred P1;\n\t"
            "WL_%=:\n\t"
            "mbarrier.try_wait.parity.acquire.cta.shared::cta.b64 P1, [%0], %1, 0x989680;\n\t"
            "@P1 bra.uni WD_%=;\n\t"
            "bra.uni WL_%=;\n\t"
            "WD_%=:\n\t}"
            :: "r"(mbar), "r"(parity) : "memory");
    }
}
__device__ __forceinline__ void fence_proxy_async_cta() {
    asm volatile("fence.proxy.async.shared::cta;" ::: "memory");
}
__device__ __forceinline__ uint32_t elect_one() {
    uint32_t pred;
    asm volatile(
        "{\n\t.reg .pred p;\n\t"
        "elect.sync _|p, 0xFFFFFFFF;\n\t"
        "selp.b32 %0, 1, 0, p;\n\t}"
        : "=r"(pred));
    return pred;
}

struct St { float h, c, n, m; };

__device__ __forceinline__ float gate_update(St &s, float iraw, float fraw,
                                             float zraw, float oraw, int t) {
    float e   = __expf(-fabsf(fraw));
    float lf  = s.m + (fraw < 0.f ? fraw : 0.f) - __logf(1.f + e);
    float mn  = (t == 0) ? iraw : fmaxf(iraw, lf);   // all(n==0) only at t=0
    float og  = __fdividef(1.f, 1.f + __expf(-oraw));
    float ig  = __expf(iraw - mn);
    float fg  = __expf(lf - mn);
    float t2  = __expf(2.f * zraw);                  // tanh(z) = 1 - 2/(1+e^{2z})
    float th  = 1.f - __fdividef(2.f, t2 + 1.f);
    float cn  = fg * s.c + ig * th;
    float nn  = fg * s.h + ig;                       // reference uses h here
    float hn  = __fdividef(og * cn, nn);
    s.c = cn; s.n = nn; s.m = mn; s.h = hn;
    return hn;
}

__global__ __launch_bounds__(TPB, 1) __cluster_dims__(CLUSTER, 1, 1)
void slstm_kernel(
    const float* __restrict__ x,     // (512, 16, 4096)
    const float* __restrict__ rk,    // (4, 256, 4, 256)
    const float* __restrict__ bias,  // flat 4096
    float* __restrict__ out)         // outs (512,16,1024) ++ final (4,16,1024)
{
    // h tile, double-buffered, rank-major: [buf][rank(8)][bl(4)][8 float4]
    __shared__ float4 sT[2][256];
    // outgoing h staging: [buf][bl(4)][8 float4] = 512 B each
    __shared__ float4 sStage[2][32];
    __shared__ float  sRaw[32 * SRS + 4];
    __shared__ unsigned long long mbar[2];

    const int c     = blockIdx.x;      // cluster = (head, bg), rank = cg
    const int head  = c >> 5;
    const int bg    = (c >> 3) & 3;
    const int cg    = c & 7;
    const int dd0   = cg << 5;
    const int b0    = bg << 2;
    const int hbase = head << 8;
    const int tid   = threadIdx.x;
    const int wq    = tid >> 5;
    const int lane  = tid & 31;
    const int rq    = lane & 3;        // channel within warp
    const int ks    = lane >> 2;       // k-slice == producer rank
    const int ch_t  = (wq << 2) + rq;  // GEMM channel (0..31)
    const int s0    = ks & 1, s1 = (ks >> 1) & 1, s2 = (ks >> 2) & 1;

    // ---- one-time W gather into registers (R8/R13-verified formula) ----
    float Wf[128];   // [(i*8+j)*4 + e], gate i, d = 32ks + 4j + e
    {
        const int dd  = dd0 + ch_t;
        const int gx  = dd >> 6;
        const int bbs = (dd & 63) << 2;
        #pragma unroll
        for (int i = 0; i < 4; ++i)
            #pragma unroll
            for (int j = 0; j < 8; ++j)
                #pragma unroll
                for (int e = 0; e < 4; ++e) {
                    int d  = 32 * ks + 4 * j + e;
                    int a  = ((d & 63) << 2) + i;
                    int bb = bbs + (d >> 6);
                    Wf[(i * 8 + j) * 4 + e] =
                        __ldg(&rk[((hbase + a) * 4 + gx) * 256 + bb]);
                }
    }
    const unsigned long long* W2 = (const unsigned long long*)Wf;

    // ---- elementwise role: tid<128 owns (channel ch_u, batch b0+bl_u) ----
    const int ch_u = tid >> 2;
    const int bl_u = tid & 3;
    const int q_u  = hbase + dd0 + ch_u;
    float bias_g[4];
    #pragma unroll
    for (int g = 0; g < 4; ++g) bias_g[g] = bias[(g << 10) + q_u];
    St st = {0.f, 0.f, 0.f, 0.f};

    // staging float index (R13-verified): f4 slot bl*8 + ((ch>>2)^cg), elem ch&3
    const int stageIdx = ((bl_u << 3) + (((ch_u >> 2) ^ cg) & 7)) * 4 + (ch_u & 3);

    const uint32_t tileAddr  = smem_u32(&sT[0][0]);
    const uint32_t stageAddr = smem_u32(&sStage[0][0]);
    const uint32_t mbarAddr  = smem_u32(&mbar[0]);
    // hoisted remote addresses: this warp pushes only to rank wq
    const uint32_t rTile = mapa_u32(tileAddr, (uint32_t)wq) + (uint32_t)(cg * 512);
    const uint32_t rMbar = mapa_u32(mbarAddr, (uint32_t)wq);

    if (tid == 0) { mbar_init(mbarAddr, 1); mbar_init(mbarAddr + 8, 1); }
    {
        float4 z = make_float4(0.f, 0.f, 0.f, 0.f);
        for (int i = tid; i < 256; i += TPB) sT[0][i] = z;
    }
    __syncthreads();
    asm volatile("barrier.cluster.arrive.aligned;" ::: "memory");
    asm volatile("barrier.cluster.wait.aligned;"   ::: "memory");

    int ph0 = 0, ph1 = 0;
    const unsigned long long* sT2 = (const unsigned long long*)&sT[0][0];

    // preload x for t=0
    float xr[4];
    if (tid < 128) {
        const float* xb = x + (size_t)(b0 + bl_u) * 4096 + q_u;
        #pragma unroll
        for (int g = 0; g < 4; ++g) xr[g] = __ldg(xb + (g << 10));
    }

    for (int t = 0; t < T_STEPS; ++t) {
        const int nb = t & 1;

        // arm the other buffer before the wait (safe: peer's push for it trails
        // the slowest t-1 push by a full GEMM+elem, our arm trails it by ~0)
        if (tid == 0 && t + 1 < T_STEPS)
            mbar_expect_tx(mbarAddr + ((t + 1) & 1) * 8, TXB);

        if (t > 0) {
            mbar_wait(mbarAddr + nb * 8, nb ? ph1 : ph0);
            if (nb) ph1 ^= 1; else ph0 ^= 1;
        }

        // prefetch x for t+1 (a full step of lead time)
        float xn[4];
        if (tid < 128 && t + 1 < T_STEPS) {
            const float* xb = x + (size_t)((t + 1) * BATCH + b0 + bl_u) * 4096 + q_u;
            #pragma unroll
            for (int g = 0; g < 4; ++g) xn[g] = __ldg(xb + (g << 10));
        }

        // ---- GEMM: 4 gates x 4 batches, k-slice = rank ks ----
        const unsigned long long* sB = sT2 + nb * (256 * 2);
        unsigned long long acc[16];
        #pragma unroll
        for (int q = 0; q < 16; ++q) acc[q] = 0ull;
        #pragma unroll
        for (int j = 0; j < 8; ++j) {
            int jj = (j ^ ks) & 7;
            unsigned long long hlo[4], hhi[4];
            #pragma unroll
            for (int bl = 0; bl < 4; ++bl) {
                int idx = ((ks << 5) + (bl << 3) + jj) << 1;
                hlo[bl] = sB[idx];
                hhi[bl] = sB[idx + 1];
            }
            #pragma unroll
            for (int i = 0; i < 4; ++i) {
                unsigned long long wlo = W2[(i * 8 + j) * 2];
                unsigned long long whi = W2[(i * 8 + j) * 2 + 1];
                #pragma unroll
                for (int bl = 0; bl < 4; ++bl) {
                    ffma2(acc[i * 4 + bl], wlo, hlo[bl]);
                    ffma2(acc[i * 4 + bl], whi, hhi[bl]);
                }
            }
        }

        // ---- butterfly reduce-scatter over ks (masks 4, 8, 16) ----
        {
            float v[16];
            #pragma unroll
            for (int q = 0; q < 16; ++q) v[q] = fold2(acc[q]);
            float w[8];
            #pragma unroll
            for (int k = 0; k < 8; ++k) {
                float send = s0 ? v[k] : v[k + 8];
                float keep = s0 ? v[k + 8] : v[k];
                w[k] = keep + __shfl_xor_sync(0xffffffffu, send, 4);
            }
            float u[4];
            #pragma unroll
            for (int k = 0; k < 4; ++k) {
                float send = s1 ? w[k] : w[k + 4];
                float keep = s1 ? w[k + 4] : w[k];
                u[k] = keep + __shfl_xor_sync(0xffffffffu, send, 8);
            }
            #pragma unroll
            for (int k = 0; k < 2; ++k) {
                float send = s2 ? u[k] : u[k + 2];
                float keep = s2 ? u[k + 2] : u[k];
                float z = keep + __shfl_xor_sync(0xffffffffu, send, 16);
                int q = (s0 << 3) + (s1 << 2) + (s2 << 1) + k;  // q = i*4 + bl
                sRaw[ch_t * SRS + q] = z;
            }
        }
        __syncthreads();

        // ---- elementwise (warps 0-3) -> staging ----
        float hn = 0.f;
        if (tid < 128) {
            const float* rw = &sRaw[ch_u * SRS + bl_u];
            float iraw = rw[ 0] + xr[0] + bias_g[0];
            float fraw = rw[ 4] + xr[1] + bias_g[1];
            float zraw = rw[ 8] + xr[2] + bias_g[2];
            float oraw = rw[12] + xr[3] + bias_g[3];
            hn = gate_update(st, iraw, fraw, zraw, oraw, t);
            ((float*)&sStage[nb][0])[stageIdx] = hn;
        }
        __syncthreads();

        // ---- parallel push: warp wq copies our 512B block to rank wq ----
        if (t + 1 < T_STEPS) {
            if (elect_one()) {
                fence_proxy_async_cta();
                bulk_copy_s2s(rTile + (uint32_t)(((t + 1) & 1) * 4096),
                              stageAddr + (uint32_t)nb * 512u,
                              512u,
                              rMbar + (uint32_t)(((t + 1) & 1) * 8));
            }
        }
        // out store + x reg rotate (off the exchange-critical path)
        if (tid < 128) {
            __stcg(&out[(size_t)(t * BATCH + b0 + bl_u) * HID + q_u], hn);
            xr[0] = xn[0]; xr[1] = xn[1]; xr[2] = xn[2]; xr[3] = xn[3];
        }
    }

    if (tid < 128) {
        const size_t FS = (size_t)T_STEPS * BATCH * HID;
        const size_t o  = (size_t)(b0 + bl_u) * HID + q_u;
        out[FS + 0 * BATCH * HID + o] = st.h;
        out[FS + 1 * BATCH * HID + o] = st.c;
        out[FS + 2 * BATCH * HID + o] = st.n;
        out[FS + 3 * BATCH * HID + o] = st.m;
    }
    // last-step pushes skipped -> nothing in flight at exit
}

extern "C" void kernel_launch(void* const* d_in, const int* in_sizes, int n_in,
                              void* d_out, int out_size) {
    const float* x    = (const float*)d_in[0];
    const float* rk   = (const float*)d_in[1];
    const float* bias = (const float*)d_in[2];
    float* out        = (float*)d_out;

    slstm_kernel<<<128, TPB>>>(x, rk, bias, out);
}